// round 7
// baseline (speedup 1.0000x reference)
#include <cuda_runtime.h>
#include <cuda_bf16.h>
#include <math.h>
#include <stdint.h>

// Problem constants
#define S_   1024
#define H_   2880
#define NH_  64
#define NKV_ 8
#define HD_  64
#define QKV_N_ 5120              // (NH + 2*NKV) * HD
#define KOFF_  4096              // NH*HD
#define VOFF_  4608              // NH*HD + NKV*HD
#define ATTN_N_ 4096             // NH*HD
#define SCALE_ 0.125f            // HD^-0.5

// ---------------------------------------------------------------------------
// Scratch (allocation-free: __device__ globals)
// ---------------------------------------------------------------------------
__device__ float g_qkv[S_ * QKV_N_];                    // 20 MB (pre-rope)
__device__ __nv_bfloat16 g_wqh[QKV_N_ * H_];            // qkv_w hi plane
__device__ __nv_bfloat16 g_wql[QKV_N_ * H_];            // qkv_w lo plane
__device__ __nv_bfloat16 g_woh[H_ * ATTN_N_];           // o_w hi
__device__ __nv_bfloat16 g_wol[H_ * ATTN_N_];           // o_w lo
__device__ __nv_bfloat16 g_xh[S_ * H_];                 // hidden hi
__device__ __nv_bfloat16 g_xl[S_ * H_];                 // hidden lo
__device__ __nv_bfloat16 g_qh[S_ * NH_ * HD_];          // roped Q hi
__device__ __nv_bfloat16 g_ql[S_ * NH_ * HD_];
__device__ __nv_bfloat16 g_kh[S_ * NKV_ * HD_];         // roped K hi
__device__ __nv_bfloat16 g_kl[S_ * NKV_ * HD_];
__device__ __nv_bfloat16 g_ah[S_ * ATTN_N_];            // attn out hi
__device__ __nv_bfloat16 g_al[S_ * ATTN_N_];

// ---------------------------------------------------------------------------
// Helpers
// ---------------------------------------------------------------------------
__device__ __forceinline__ void mma16816(float* c, const uint32_t* a, const uint32_t* b) {
    asm volatile(
        "mma.sync.aligned.m16n8k16.row.col.f32.bf16.bf16.f32 "
        "{%0,%1,%2,%3}, {%4,%5,%6,%7}, {%8,%9}, {%0,%1,%2,%3};\n"
        : "+f"(c[0]), "+f"(c[1]), "+f"(c[2]), "+f"(c[3])
        : "r"(a[0]), "r"(a[1]), "r"(a[2]), "r"(a[3]), "r"(b[0]), "r"(b[1]));
}

__device__ __forceinline__ void split2(float x, float y, uint32_t& hi, uint32_t& lo) {
    __nv_bfloat16 hx = __float2bfloat16(x);
    __nv_bfloat16 hy = __float2bfloat16(y);
    __nv_bfloat16 lx = __float2bfloat16(x - __bfloat162float(hx));
    __nv_bfloat16 ly = __float2bfloat16(y - __bfloat162float(hy));
    hi = ((uint32_t)__bfloat16_as_ushort(hy) << 16) | (uint32_t)__bfloat16_as_ushort(hx);
    lo = ((uint32_t)__bfloat16_as_ushort(ly) << 16) | (uint32_t)__bfloat16_as_ushort(lx);
}

__device__ __forceinline__ uint32_t smemu32(const void* p) {
    return (uint32_t)__cvta_generic_to_shared(p);
}

#define LDSM4(R0, R1, R2, R3, addr) \
    asm volatile("ldmatrix.sync.aligned.m8n8.x4.shared.b16 {%0,%1,%2,%3}, [%4];" \
                 : "=r"(R0), "=r"(R1), "=r"(R2), "=r"(R3) : "r"(addr))

#define CP16(dst, src) \
    asm volatile("cp.async.cg.shared.global [%0], [%1], 16;" :: "r"(dst), "l"(src))

// ---------------------------------------------------------------------------
// fp32 -> bf16 hi/lo plane split (vectorized)
// ---------------------------------------------------------------------------
__global__ __launch_bounds__(256)
void split_f32(const float* __restrict__ in, __nv_bfloat16* __restrict__ hi,
               __nv_bfloat16* __restrict__ lo, int n)
{
    int i = (blockIdx.x * 256 + threadIdx.x) * 4;
    if (i >= n) return;
    float4 v = *(const float4*)&in[i];
    uint32_t h0, l0, h1, l1;
    split2(v.x, v.y, h0, l0);
    split2(v.z, v.w, h1, l1);
    uint32_t* ph = (uint32_t*)&hi[i];
    uint32_t* pl = (uint32_t*)&lo[i];
    ph[0] = h0; ph[1] = h1;
    pl[0] = l0; pl[1] = l1;
}

// ---------------------------------------------------------------------------
// Tensor-core GEMM (NT) on pre-split bf16 planes. 3-pass hi/lo.
// C[m,n] = sum_k A[m,k]*B[n,k].  BM=128, BN=64, BK=32, 256 thr (8 warps).
// cp.async double-buffered smem, ldmatrix fragment loads.
// ---------------------------------------------------------------------------
#define BM 128
#define BN 64
#define BK 32
#define ASTR 40                       // elems/row (32 data + 8 pad) = 80B, 16B-aligned, conflict-free
#define BUF_ELEMS (2 * BM * ASTR + 2 * BN * ASTR)   // 15360 elems = 30720 B per buffer

__global__ __launch_bounds__(256)
void gemm_planes(const __nv_bfloat16* __restrict__ Ah, const __nv_bfloat16* __restrict__ Al,
                 const __nv_bfloat16* __restrict__ Bh, const __nv_bfloat16* __restrict__ Bl,
                 float* __restrict__ C, int M, int N, int K)
{
    extern __shared__ __nv_bfloat16 sm[];    // [2][BUF_ELEMS]

    const int tid  = threadIdx.x;
    const int wid  = tid >> 5;
    const int lane = tid & 31;
    const int g    = lane >> 2;
    const int cq   = lane & 3;
    const int wm   = (wid & 3) * 32;
    const int wn   = (wid >> 2) * 32;
    const int bm   = blockIdx.y * BM;
    const int bn   = blockIdx.x * BN;

    float acc[2][4][4];
#pragma unroll
    for (int mt = 0; mt < 2; mt++)
#pragma unroll
        for (int nt = 0; nt < 4; nt++)
#pragma unroll
            for (int i = 0; i < 4; i++) acc[mt][nt][i] = 0.f;

    const int ntile = K / BK;

    // --- async tile loader: 6 x 16B per thread ---
    auto load_tile = [&](int t, int buf) {
        const int k0 = t * BK;
        __nv_bfloat16* s = sm + buf * BUF_ELEMS;
#pragma unroll
        for (int i = 0; i < 4; i++) {                  // A: 1024 chunks
            int c   = tid + i * 256;
            int p   = c >> 9;
            int r   = (c & 511) >> 2;
            int col = (c & 3) * 8;
            const __nv_bfloat16* src = (p ? Al : Ah) + (size_t)(bm + r) * K + k0 + col;
            CP16(smemu32(s + p * BM * ASTR + r * ASTR + col), src);
        }
#pragma unroll
        for (int i = 0; i < 2; i++) {                  // B: 512 chunks
            int c   = tid + i * 256;
            int p   = c >> 8;
            int r   = (c & 255) >> 2;
            int col = (c & 3) * 8;
            const __nv_bfloat16* src = (p ? Bl : Bh) + (size_t)(bn + r) * K + k0 + col;
            CP16(smemu32(s + 2 * BM * ASTR + p * BN * ASTR + r * ASTR + col), src);
        }
        asm volatile("cp.async.commit_group;" ::);
    };

    load_tile(0, 0);

    const int lr  = lane & 15;
    const int hb  = (lane >> 4) * 8;
    const int l8  = lane & 7;
    const int sel = lane >> 3;

    for (int t = 0; t < ntile; t++) {
        asm volatile("cp.async.wait_group 0;" ::);
        __syncthreads();
        if (t + 1 < ntile) load_tile(t + 1, (t + 1) & 1);

        const __nv_bfloat16* s = sm + (t & 1) * BUF_ELEMS;
#pragma unroll
        for (int kk = 0; kk < 2; kk++) {
            uint32_t ah[2][4], alv[2][4];
#pragma unroll
            for (int mt = 0; mt < 2; mt++) {
                uint32_t addr = smemu32(s + (wm + mt * 16 + lr) * ASTR + kk * 16 + hb);
                LDSM4(ah[mt][0], ah[mt][1], ah[mt][2], ah[mt][3], addr);
                addr = smemu32(s + BM * ASTR + (wm + mt * 16 + lr) * ASTR + kk * 16 + hb);
                LDSM4(alv[mt][0], alv[mt][1], alv[mt][2], alv[mt][3], addr);
            }
#pragma unroll
            for (int np = 0; np < 2; np++) {
                const int brow = wn + np * 16 + ((sel >> 1) << 3) + l8;
                const int bcol = kk * 16 + (sel & 1) * 8;
                uint32_t bh[4], bl[4];
                LDSM4(bh[0], bh[1], bh[2], bh[3],
                      smemu32(s + 2 * BM * ASTR + brow * ASTR + bcol));
                LDSM4(bl[0], bl[1], bl[2], bl[3],
                      smemu32(s + 2 * BM * ASTR + BN * ASTR + brow * ASTR + bcol));
#pragma unroll
                for (int mt = 0; mt < 2; mt++) {
                    mma16816(acc[mt][2 * np],     ah[mt],  &bh[0]);
                    mma16816(acc[mt][2 * np],     ah[mt],  &bl[0]);
                    mma16816(acc[mt][2 * np],     alv[mt], &bh[0]);
                    mma16816(acc[mt][2 * np + 1], ah[mt],  &bh[2]);
                    mma16816(acc[mt][2 * np + 1], ah[mt],  &bl[2]);
                    mma16816(acc[mt][2 * np + 1], alv[mt], &bh[2]);
                }
            }
        }
    }

#pragma unroll
    for (int mt = 0; mt < 2; mt++)
#pragma unroll
        for (int nt = 0; nt < 4; nt++) {
            int row = bm + wm + mt * 16 + g;
            int col = bn + wn + nt * 8 + cq * 2;
            *(float2*)&C[(size_t)row * N + col]       = make_float2(acc[mt][nt][0], acc[mt][nt][1]);
            *(float2*)&C[(size_t)(row + 8) * N + col] = make_float2(acc[mt][nt][2], acc[mt][nt][3]);
        }
}

// ---------------------------------------------------------------------------
// RoPE + split to bf16 planes. One 32-thread block per (s, q-or-k head).
// Reads g_qkv fp32 (pre-rope), writes g_qh/ql or g_kh/kl.
// ---------------------------------------------------------------------------
__global__ void rope_split(const int* __restrict__ positions)
{
    const int row = blockIdx.x;                  // 0 .. S*(NH+NKV)-1
    const int s  = row / (NH_ + NKV_);
    const int hh = row % (NH_ + NKV_);
    const int i  = threadIdx.x;                  // 0..31

    const float pos = (float)positions[s];
    const float inv_freq = powf(10000.0f, -(float)i / 32.0f);
    const float ang = pos * inv_freq;
    float c, sn;
    sincosf(ang, &sn, &c);

    const float* src;
    __nv_bfloat16 *dh, *dl;
    if (hh < NH_) {
        src = &g_qkv[(size_t)s * QKV_N_ + hh * HD_];
        dh = &g_qh[(size_t)s * (NH_ * HD_) + hh * HD_];
        dl = &g_ql[(size_t)s * (NH_ * HD_) + hh * HD_];
    } else {
        const int kvh = hh - NH_;
        src = &g_qkv[(size_t)s * QKV_N_ + KOFF_ + kvh * HD_];
        dh = &g_kh[(size_t)s * (NKV_ * HD_) + kvh * HD_];
        dl = &g_kl[(size_t)s * (NKV_ * HD_) + kvh * HD_];
    }
    const float x1 = src[i];
    const float x2 = src[i + 32];
    const float r1 = x1 * c - x2 * sn;
    const float r2 = x2 * c + x1 * sn;
    __nv_bfloat16 h1 = __float2bfloat16(r1);
    __nv_bfloat16 h2 = __float2bfloat16(r2);
    dh[i]      = h1;
    dh[i + 32] = h2;
    dl[i]      = __float2bfloat16(r1 - __bfloat162float(h1));
    dl[i + 32] = __float2bfloat16(r2 - __bfloat162float(h2));
}

// ---------------------------------------------------------------------------
// Flash attention (tensor cores, hi/lo 3-pass), online softmax, sinks.
// Q/K staged from pre-split planes; V split from g_qkv (transposed staging).
// Output written as bf16 hi/lo planes for the O-projection.
// ---------------------------------------------------------------------------
#define VSTR 36

__global__ __launch_bounds__(128)
void flash_attn(const float* __restrict__ sinks)
{
    __shared__ uint32_t Qs[2][64 * VSTR];
    __shared__ uint32_t Ks[2][64 * VSTR];
    __shared__ uint32_t Vs[2][64 * VSTR];

    const int h   = blockIdx.y;
    const int qt  = (S_ / 64 - 1) - blockIdx.x;   // heavy tiles first
    const int q0  = qt * 64;
    const int kv  = h >> 3;
    const int tid = threadIdx.x;
    const int wid = tid >> 5;
    const int lane = tid & 31;
    const int g   = lane >> 2;
    const int cq  = lane & 3;
    const float sink = sinks[h];

    // ---- stage Q tile from planes (plain word copies) ----
    {
        const int row = tid >> 1, e = tid & 1;
        const uint32_t* qh = (const uint32_t*)&g_qh[(size_t)(q0 + row) * (NH_ * HD_) + h * HD_ + e * 32];
        const uint32_t* ql = (const uint32_t*)&g_ql[(size_t)(q0 + row) * (NH_ * HD_) + h * HD_ + e * 32];
#pragma unroll
        for (int w = 0; w < 16; w++) {
            Qs[0][row * VSTR + e * 16 + w] = qh[w];
            Qs[1][row * VSTR + e * 16 + w] = ql[w];
        }
    }
    __syncthreads();

    // ---- Q fragments in registers ----
    uint32_t qa[2][4][4];
    {
        const int r0 = (wid * 16 + g) * VSTR;
        const int r8 = r0 + 8 * VSTR;
#pragma unroll
        for (int p = 0; p < 2; p++)
#pragma unroll
            for (int kt = 0; kt < 4; kt++) {
                const int w0 = kt * 8 + cq;
                qa[p][kt][0] = Qs[p][r0 + w0];
                qa[p][kt][1] = Qs[p][r8 + w0];
                qa[p][kt][2] = Qs[p][r0 + w0 + 4];
                qa[p][kt][3] = Qs[p][r8 + w0 + 4];
            }
    }

    float oacc[8][4];
#pragma unroll
    for (int nt = 0; nt < 8; nt++)
#pragma unroll
        for (int i = 0; i < 4; i++) oacc[nt][i] = 0.f;
    float m0 = -INFINITY, m8 = -INFINITY;
    float l0 = 0.f, l8 = 0.f;

    const int row_g  = q0 + wid * 16 + g;
    const int row_g8 = row_g + 8;
    const int ntiles = qt + 1;

    for (int t = 0; t < ntiles; t++) {
        const int k0 = t * 64;
        __syncthreads();

        // stage K tile from planes
        {
            const int key = tid >> 1, e = tid & 1;
            const uint32_t* kh = (const uint32_t*)&g_kh[(size_t)(k0 + key) * (NKV_ * HD_) + kv * HD_ + e * 32];
            const uint32_t* kl = (const uint32_t*)&g_kl[(size_t)(k0 + key) * (NKV_ * HD_) + kv * HD_ + e * 32];
#pragma unroll
            for (int w = 0; w < 16; w++) {
                Ks[0][key * VSTR + e * 16 + w] = kh[w];
                Ks[1][key * VSTR + e * 16 + w] = kl[w];
            }
        }
        // stage V transposed: Vs[dim][key-pair word] (split from fp32 g_qkv)
        {
            const int j = lane;
#pragma unroll
            for (int i = 0; i < 4; i++) {
                const int d = wid * 16 + i * 4;
                const float* v0 = &g_qkv[(size_t)(k0 + 2 * j) * QKV_N_ + VOFF_ + kv * HD_ + d];
                const float* v1 = v0 + QKV_N_;
                float4 a = *(const float4*)v0;
                float4 b = *(const float4*)v1;
                uint32_t hw, lw;
                split2(a.x, b.x, hw, lw); Vs[0][(d + 0) * VSTR + j] = hw; Vs[1][(d + 0) * VSTR + j] = lw;
                split2(a.y, b.y, hw, lw); Vs[0][(d + 1) * VSTR + j] = hw; Vs[1][(d + 1) * VSTR + j] = lw;
                split2(a.z, b.z, hw, lw); Vs[0][(d + 2) * VSTR + j] = hw; Vs[1][(d + 2) * VSTR + j] = lw;
                split2(a.w, b.w, hw, lw); Vs[0][(d + 3) * VSTR + j] = hw; Vs[1][(d + 3) * VSTR + j] = lw;
            }
        }
        __syncthreads();

        // ---- S = Q K^T ----
        float sacc[8][4];
#pragma unroll
        for (int nt = 0; nt < 8; nt++)
#pragma unroll
            for (int i = 0; i < 4; i++) sacc[nt][i] = 0.f;

#pragma unroll
        for (int kt = 0; kt < 4; kt++) {
#pragma unroll
            for (int nt = 0; nt < 8; nt++) {
                const int r0 = (nt * 8 + g) * VSTR + kt * 8 + cq;
                uint32_t bhf[2], blf[2];
                bhf[0] = Ks[0][r0]; bhf[1] = Ks[0][r0 + 4];
                blf[0] = Ks[1][r0]; blf[1] = Ks[1][r0 + 4];
                mma16816(sacc[nt], qa[0][kt], bhf);
                mma16816(sacc[nt], qa[0][kt], blf);
                mma16816(sacc[nt], qa[1][kt], bhf);
            }
        }

        // ---- scale + causal mask (last tile only) ----
        const bool last = (t == ntiles - 1);
#pragma unroll
        for (int nt = 0; nt < 8; nt++) {
            const int c0 = k0 + nt * 8 + 2 * cq;
#pragma unroll
            for (int i = 0; i < 4; i++) sacc[nt][i] *= SCALE_;
            if (last) {
                if (c0     > row_g)  sacc[nt][0] = -INFINITY;
                if (c0 + 1 > row_g)  sacc[nt][1] = -INFINITY;
                if (c0     > row_g8) sacc[nt][2] = -INFINITY;
                if (c0 + 1 > row_g8) sacc[nt][3] = -INFINITY;
            }
        }

        // ---- online softmax update ----
        float tm0 = -INFINITY, tm8 = -INFINITY;
#pragma unroll
        for (int nt = 0; nt < 8; nt++) {
            tm0 = fmaxf(tm0, fmaxf(sacc[nt][0], sacc[nt][1]));
            tm8 = fmaxf(tm8, fmaxf(sacc[nt][2], sacc[nt][3]));
        }
        tm0 = fmaxf(tm0, __shfl_xor_sync(0xffffffffu, tm0, 1));
        tm0 = fmaxf(tm0, __shfl_xor_sync(0xffffffffu, tm0, 2));
        tm8 = fmaxf(tm8, __shfl_xor_sync(0xffffffffu, tm8, 1));
        tm8 = fmaxf(tm8, __shfl_xor_sync(0xffffffffu, tm8, 2));

        const float m0n = fmaxf(m0, tm0);
        const float m8n = fmaxf(m8, tm8);
        const float a0 = __expf(m0 - m0n);
        const float a8 = __expf(m8 - m8n);
        m0 = m0n; m8 = m8n;
        l0 *= a0; l8 *= a8;
#pragma unroll
        for (int nt = 0; nt < 8; nt++) {
            oacc[nt][0] *= a0; oacc[nt][1] *= a0;
            oacc[nt][2] *= a8; oacc[nt][3] *= a8;
        }

#pragma unroll
        for (int nt = 0; nt < 8; nt++) {
            float p0 = (sacc[nt][0] == -INFINITY) ? 0.f : __expf(sacc[nt][0] - m0);
            float p1 = (sacc[nt][1] == -INFINITY) ? 0.f : __expf(sacc[nt][1] - m0);
            float p2 = (sacc[nt][2] == -INFINITY) ? 0.f : __expf(sacc[nt][2] - m8);
            float p3 = (sacc[nt][3] == -INFINITY) ? 0.f : __expf(sacc[nt][3] - m8);
            sacc[nt][0] = p0; sacc[nt][1] = p1; sacc[nt][2] = p2; sacc[nt][3] = p3;
            l0 += p0 + p1;
            l8 += p2 + p3;
        }

        // ---- O += P V ----
#pragma unroll
        for (int kt = 0; kt < 4; kt++) {
            uint32_t pah[4], pal[4];
            split2(sacc[2 * kt][0],     sacc[2 * kt][1],     pah[0], pal[0]);
            split2(sacc[2 * kt][2],     sacc[2 * kt][3],     pah[1], pal[1]);
            split2(sacc[2 * kt + 1][0], sacc[2 * kt + 1][1], pah[2], pal[2]);
            split2(sacc[2 * kt + 1][2], sacc[2 * kt + 1][3], pah[3], pal[3]);
#pragma unroll
            for (int nt = 0; nt < 8; nt++) {
                const int r0 = (nt * 8 + g) * VSTR + kt * 8 + cq;
                uint32_t vhf[2], vlf[2];
                vhf[0] = Vs[0][r0]; vhf[1] = Vs[0][r0 + 4];
                vlf[0] = Vs[1][r0]; vlf[1] = Vs[1][r0 + 4];
                mma16816(oacc[nt], pah, vhf);
                mma16816(oacc[nt], pah, vlf);
                mma16816(oacc[nt], pal, vhf);
            }
        }
    }

    // ---- finalize with sink; write bf16 hi/lo planes ----
    {
        const float m0n = fmaxf(m0, sink);
        const float m8n = fmaxf(m8, sink);
        const float a0 = __expf(m0 - m0n);
        const float a8 = __expf(m8 - m8n);
        l0 *= a0; l8 *= a8;
        l0 += __shfl_xor_sync(0xffffffffu, l0, 1);
        l0 += __shfl_xor_sync(0xffffffffu, l0, 2);
        l8 += __shfl_xor_sync(0xffffffffu, l8, 1);
        l8 += __shfl_xor_sync(0xffffffffu, l8, 2);
        const float inv0 = a0 / (l0 + __expf(sink - m0n));
        const float inv8 = a8 / (l8 + __expf(sink - m8n));
#pragma unroll
        for (int nt = 0; nt < 8; nt++) {
            const int col = h * HD_ + nt * 8 + 2 * cq;
            uint32_t hw, lw;
            split2(oacc[nt][0] * inv0, oacc[nt][1] * inv0, hw, lw);
            *(uint32_t*)&g_ah[(size_t)row_g * ATTN_N_ + col] = hw;
            *(uint32_t*)&g_al[(size_t)row_g * ATTN_N_ + col] = lw;
            split2(oacc[nt][2] * inv8, oacc[nt][3] * inv8, hw, lw);
            *(uint32_t*)&g_ah[(size_t)row_g8 * ATTN_N_ + col] = hw;
            *(uint32_t*)&g_al[(size_t)row_g8 * ATTN_N_ + col] = lw;
        }
    }
}

// ---------------------------------------------------------------------------
// Launch
// ---------------------------------------------------------------------------
extern "C" void kernel_launch(void* const* d_in, const int* in_sizes, int n_in,
                              void* d_out, int out_size)
{
    const int*   positions = (const int*)d_in[0];
    const float* hidden    = (const float*)d_in[1];
    const float* qkv_w     = (const float*)d_in[2];
    const float* o_w       = (const float*)d_in[3];
    const float* sinks     = (const float*)d_in[4];
    float*       out       = (float*)d_out;

    static bool attr_done = false;
    if (!attr_done) {
        cudaFuncSetAttribute(gemm_planes, cudaFuncAttributeMaxDynamicSharedMemorySize,
                             2 * BUF_ELEMS * (int)sizeof(__nv_bfloat16));
        attr_done = true;
    }

    void *p;
    cudaGetSymbolAddress(&p, g_qkv);  float* qkv = (float*)p;
    cudaGetSymbolAddress(&p, g_wqh);  __nv_bfloat16* wqh = (__nv_bfloat16*)p;
    cudaGetSymbolAddress(&p, g_wql);  __nv_bfloat16* wql = (__nv_bfloat16*)p;
    cudaGetSymbolAddress(&p, g_woh);  __nv_bfloat16* woh = (__nv_bfloat16*)p;
    cudaGetSymbolAddress(&p, g_wol);  __nv_bfloat16* wol = (__nv_bfloat16*)p;
    cudaGetSymbolAddress(&p, g_xh);   __nv_bfloat16* xh  = (__nv_bfloat16*)p;
    cudaGetSymbolAddress(&p, g_xl);   __nv_bfloat16* xl  = (__nv_bfloat16*)p;
    cudaGetSymbolAddress(&p, g_ah);   __nv_bfloat16* ah  = (__nv_bfloat16*)p;
    cudaGetSymbolAddress(&p, g_al);   __nv_bfloat16* al  = (__nv_bfloat16*)p;

    const int smem = 2 * BUF_ELEMS * (int)sizeof(__nv_bfloat16);

    // 0) pre-split weights + activations to bf16 planes
    split_f32<<<(QKV_N_ * H_) / 1024, 256>>>(qkv_w, wqh, wql, QKV_N_ * H_);
    split_f32<<<(H_ * ATTN_N_) / 1024, 256>>>(o_w, woh, wol, H_ * ATTN_N_);
    split_f32<<<(S_ * H_) / 1024, 256>>>(hidden, xh, xl, S_ * H_);

    // 1) QKV projection: [1024,2880] @ [5120,2880]^T -> g_qkv fp32
    gemm_planes<<<dim3(QKV_N_ / BN, S_ / BM), 256, smem>>>(xh, xl, wqh, wql, qkv, S_, QKV_N_, H_);

    // 2) RoPE + split Q/K to planes
    rope_split<<<S_ * (NH_ + NKV_), 32>>>(positions);

    // 3) Flash attention -> attn planes
    flash_attn<<<dim3(S_ / 64, NH_), 128>>>(sinks);

    // 4) O projection: attn planes @ o_w planes -> out fp32
    gemm_planes<<<dim3(H_ / BN, S_ / BM), 256, smem>>>(ah, al, woh, wol, out, S_, H_, ATTN_N_);
}

// round 8
// speedup vs baseline: 1.0016x; 1.0016x over previous
#include <cuda_runtime.h>
#include <cuda_bf16.h>
#include <math.h>
#include <stdint.h>

// Problem constants
#define S_   1024
#define H_   2880
#define NH_  64
#define NKV_ 8
#define HD_  64
#define QKV_N_ 5120              // (NH + 2*NKV) * HD
#define KOFF_  4096              // NH*HD
#define VOFF_  4608              // NH*HD + NKV*HD
#define ATTN_N_ 4096             // NH*HD
#define SCALE_ 0.125f            // HD^-0.5

// ---------------------------------------------------------------------------
// Scratch (allocation-free: __device__ globals)
// ---------------------------------------------------------------------------
__device__ float g_qkv[S_ * QKV_N_];                    // 20 MB (pre-rope)
__device__ __nv_bfloat16 g_wqh[QKV_N_ * H_];            // qkv_w hi plane
__device__ __nv_bfloat16 g_wql[QKV_N_ * H_];            // qkv_w lo plane
__device__ __nv_bfloat16 g_woh[H_ * ATTN_N_];           // o_w hi
__device__ __nv_bfloat16 g_wol[H_ * ATTN_N_];           // o_w lo
__device__ __nv_bfloat16 g_xh[S_ * H_];                 // hidden hi
__device__ __nv_bfloat16 g_xl[S_ * H_];                 // hidden lo
__device__ __nv_bfloat16 g_qh[S_ * NH_ * HD_];          // roped Q hi
__device__ __nv_bfloat16 g_ql[S_ * NH_ * HD_];
__device__ __nv_bfloat16 g_kh[S_ * NKV_ * HD_];         // roped K hi
__device__ __nv_bfloat16 g_kl[S_ * NKV_ * HD_];
__device__ __nv_bfloat16 g_ah[S_ * ATTN_N_];            // attn out hi
__device__ __nv_bfloat16 g_al[S_ * ATTN_N_];

// ---------------------------------------------------------------------------
// Helpers
// ---------------------------------------------------------------------------
__device__ __forceinline__ void mma16816(float* c, const uint32_t* a, const uint32_t* b) {
    asm volatile(
        "mma.sync.aligned.m16n8k16.row.col.f32.bf16.bf16.f32 "
        "{%0,%1,%2,%3}, {%4,%5,%6,%7}, {%8,%9}, {%0,%1,%2,%3};\n"
        : "+f"(c[0]), "+f"(c[1]), "+f"(c[2]), "+f"(c[3])
        : "r"(a[0]), "r"(a[1]), "r"(a[2]), "r"(a[3]), "r"(b[0]), "r"(b[1]));
}

__device__ __forceinline__ void split2(float x, float y, uint32_t& hi, uint32_t& lo) {
    __nv_bfloat16 hx = __float2bfloat16(x);
    __nv_bfloat16 hy = __float2bfloat16(y);
    __nv_bfloat16 lx = __float2bfloat16(x - __bfloat162float(hx));
    __nv_bfloat16 ly = __float2bfloat16(y - __bfloat162float(hy));
    hi = ((uint32_t)__bfloat16_as_ushort(hy) << 16) | (uint32_t)__bfloat16_as_ushort(hx);
    lo = ((uint32_t)__bfloat16_as_ushort(ly) << 16) | (uint32_t)__bfloat16_as_ushort(lx);
}

__device__ __forceinline__ uint32_t smemu32(const void* p) {
    return (uint32_t)__cvta_generic_to_shared(p);
}

#define LDSM4(R0, R1, R2, R3, addr) \
    asm volatile("ldmatrix.sync.aligned.m8n8.x4.shared.b16 {%0,%1,%2,%3}, [%4];" \
                 : "=r"(R0), "=r"(R1), "=r"(R2), "=r"(R3) : "r"(addr))

#define CP16(dst, src) \
    asm volatile("cp.async.cg.shared.global [%0], [%1], 16;" :: "r"(dst), "l"(src))

// ---------------------------------------------------------------------------
// fp32 -> bf16 hi/lo plane split (vectorized)
// ---------------------------------------------------------------------------
__global__ __launch_bounds__(256)
void split_f32(const float* __restrict__ in, __nv_bfloat16* __restrict__ hi,
               __nv_bfloat16* __restrict__ lo, int n)
{
    int i = (blockIdx.x * 256 + threadIdx.x) * 4;
    if (i >= n) return;
    float4 v = *(const float4*)&in[i];
    uint32_t h0, l0, h1, l1;
    split2(v.x, v.y, h0, l0);
    split2(v.z, v.w, h1, l1);
    uint32_t* ph = (uint32_t*)&hi[i];
    uint32_t* pl = (uint32_t*)&lo[i];
    ph[0] = h0; ph[1] = h1;
    pl[0] = l0; pl[1] = l1;
}

// ---------------------------------------------------------------------------
// Tensor-core GEMM (NT) on pre-split bf16 planes. 3-pass hi/lo.
// C[m,n] = sum_k A[m,k]*B[n,k].  BM=128, BN=64, BK=32, 256 thr (8 warps).
// cp.async double-buffered smem, ldmatrix fragment loads.
// ---------------------------------------------------------------------------
#define BM 128
#define BN 64
#define BK 32
#define ASTR 40                       // elems/row (32 data + 8 pad) = 80B, 16B-aligned, conflict-free
#define BUF_ELEMS (2 * BM * ASTR + 2 * BN * ASTR)   // 15360 elems = 30720 B per buffer

__global__ __launch_bounds__(256)
void gemm_planes(const __nv_bfloat16* __restrict__ Ah, const __nv_bfloat16* __restrict__ Al,
                 const __nv_bfloat16* __restrict__ Bh, const __nv_bfloat16* __restrict__ Bl,
                 float* __restrict__ C, int M, int N, int K)
{
    extern __shared__ __nv_bfloat16 sm[];    // [2][BUF_ELEMS]

    const int tid  = threadIdx.x;
    const int wid  = tid >> 5;
    const int lane = tid & 31;
    const int g    = lane >> 2;
    const int cq   = lane & 3;
    const int wm   = (wid & 3) * 32;
    const int wn   = (wid >> 2) * 32;
    const int bm   = blockIdx.y * BM;
    const int bn   = blockIdx.x * BN;

    float acc[2][4][4];
#pragma unroll
    for (int mt = 0; mt < 2; mt++)
#pragma unroll
        for (int nt = 0; nt < 4; nt++)
#pragma unroll
            for (int i = 0; i < 4; i++) acc[mt][nt][i] = 0.f;

    const int ntile = K / BK;

    // --- async tile loader: 6 x 16B per thread ---
    auto load_tile = [&](int t, int buf) {
        const int k0 = t * BK;
        __nv_bfloat16* s = sm + buf * BUF_ELEMS;
#pragma unroll
        for (int i = 0; i < 4; i++) {                  // A: 1024 chunks
            int c   = tid + i * 256;
            int p   = c >> 9;
            int r   = (c & 511) >> 2;
            int col = (c & 3) * 8;
            const __nv_bfloat16* src = (p ? Al : Ah) + (size_t)(bm + r) * K + k0 + col;
            CP16(smemu32(s + p * BM * ASTR + r * ASTR + col), src);
        }
#pragma unroll
        for (int i = 0; i < 2; i++) {                  // B: 512 chunks
            int c   = tid + i * 256;
            int p   = c >> 8;
            int r   = (c & 255) >> 2;
            int col = (c & 3) * 8;
            const __nv_bfloat16* src = (p ? Bl : Bh) + (size_t)(bn + r) * K + k0 + col;
            CP16(smemu32(s + 2 * BM * ASTR + p * BN * ASTR + r * ASTR + col), src);
        }
        asm volatile("cp.async.commit_group;" ::);
    };

    load_tile(0, 0);

    const int lr  = lane & 15;
    const int hb  = (lane >> 4) * 8;
    const int l8  = lane & 7;
    const int sel = lane >> 3;

    for (int t = 0; t < ntile; t++) {
        asm volatile("cp.async.wait_group 0;" ::);
        __syncthreads();
        if (t + 1 < ntile) load_tile(t + 1, (t + 1) & 1);

        const __nv_bfloat16* s = sm + (t & 1) * BUF_ELEMS;
#pragma unroll
        for (int kk = 0; kk < 2; kk++) {
            uint32_t ah[2][4], alv[2][4];
#pragma unroll
            for (int mt = 0; mt < 2; mt++) {
                uint32_t addr = smemu32(s + (wm + mt * 16 + lr) * ASTR + kk * 16 + hb);
                LDSM4(ah[mt][0], ah[mt][1], ah[mt][2], ah[mt][3], addr);
                addr = smemu32(s + BM * ASTR + (wm + mt * 16 + lr) * ASTR + kk * 16 + hb);
                LDSM4(alv[mt][0], alv[mt][1], alv[mt][2], alv[mt][3], addr);
            }
#pragma unroll
            for (int np = 0; np < 2; np++) {
                const int brow = wn + np * 16 + ((sel >> 1) << 3) + l8;
                const int bcol = kk * 16 + (sel & 1) * 8;
                uint32_t bh[4], bl[4];
                LDSM4(bh[0], bh[1], bh[2], bh[3],
                      smemu32(s + 2 * BM * ASTR + brow * ASTR + bcol));
                LDSM4(bl[0], bl[1], bl[2], bl[3],
                      smemu32(s + 2 * BM * ASTR + BN * ASTR + brow * ASTR + bcol));
#pragma unroll
                for (int mt = 0; mt < 2; mt++) {
                    mma16816(acc[mt][2 * np],     ah[mt],  &bh[0]);
                    mma16816(acc[mt][2 * np],     ah[mt],  &bl[0]);
                    mma16816(acc[mt][2 * np],     alv[mt], &bh[0]);
                    mma16816(acc[mt][2 * np + 1], ah[mt],  &bh[2]);
                    mma16816(acc[mt][2 * np + 1], ah[mt],  &bl[2]);
                    mma16816(acc[mt][2 * np + 1], alv[mt], &bh[2]);
                }
            }
        }
    }

#pragma unroll
    for (int mt = 0; mt < 2; mt++)
#pragma unroll
        for (int nt = 0; nt < 4; nt++) {
            int row = bm + wm + mt * 16 + g;
            int col = bn + wn + nt * 8 + cq * 2;
            *(float2*)&C[(size_t)row * N + col]       = make_float2(acc[mt][nt][0], acc[mt][nt][1]);
            *(float2*)&C[(size_t)(row + 8) * N + col] = make_float2(acc[mt][nt][2], acc[mt][nt][3]);
        }
}

// ---------------------------------------------------------------------------
// RoPE + split to bf16 planes. One 32-thread block per (s, q-or-k head).
// Reads g_qkv fp32 (pre-rope), writes g_qh/ql or g_kh/kl.
// ---------------------------------------------------------------------------
__global__ void rope_split(const int* __restrict__ positions)
{
    const int row = blockIdx.x;                  // 0 .. S*(NH+NKV)-1
    const int s  = row / (NH_ + NKV_);
    const int hh = row % (NH_ + NKV_);
    const int i  = threadIdx.x;                  // 0..31

    const float pos = (float)positions[s];
    const float inv_freq = powf(10000.0f, -(float)i / 32.0f);
    const float ang = pos * inv_freq;
    float c, sn;
    sincosf(ang, &sn, &c);

    const float* src;
    __nv_bfloat16 *dh, *dl;
    if (hh < NH_) {
        src = &g_qkv[(size_t)s * QKV_N_ + hh * HD_];
        dh = &g_qh[(size_t)s * (NH_ * HD_) + hh * HD_];
        dl = &g_ql[(size_t)s * (NH_ * HD_) + hh * HD_];
    } else {
        const int kvh = hh - NH_;
        src = &g_qkv[(size_t)s * QKV_N_ + KOFF_ + kvh * HD_];
        dh = &g_kh[(size_t)s * (NKV_ * HD_) + kvh * HD_];
        dl = &g_kl[(size_t)s * (NKV_ * HD_) + kvh * HD_];
    }
    const float x1 = src[i];
    const float x2 = src[i + 32];
    const float r1 = x1 * c - x2 * sn;
    const float r2 = x2 * c + x1 * sn;
    __nv_bfloat16 h1 = __float2bfloat16(r1);
    __nv_bfloat16 h2 = __float2bfloat16(r2);
    dh[i]      = h1;
    dh[i + 32] = h2;
    dl[i]      = __float2bfloat16(r1 - __bfloat162float(h1));
    dl[i + 32] = __float2bfloat16(r2 - __bfloat162float(h2));
}

// ---------------------------------------------------------------------------
// Flash attention (tensor cores, hi/lo 3-pass), online softmax, sinks.
// Q/K staged from pre-split planes; V split from g_qkv (transposed staging).
// Output written as bf16 hi/lo planes for the O-projection.
// ---------------------------------------------------------------------------
#define VSTR 36

__global__ __launch_bounds__(128)
void flash_attn(const float* __restrict__ sinks)
{
    __shared__ uint32_t Qs[2][64 * VSTR];
    __shared__ uint32_t Ks[2][64 * VSTR];
    __shared__ uint32_t Vs[2][64 * VSTR];

    const int h   = blockIdx.y;
    const int qt  = (S_ / 64 - 1) - blockIdx.x;   // heavy tiles first
    const int q0  = qt * 64;
    const int kv  = h >> 3;
    const int tid = threadIdx.x;
    const int wid = tid >> 5;
    const int lane = tid & 31;
    const int g   = lane >> 2;
    const int cq  = lane & 3;
    const float sink = sinks[h];

    // ---- stage Q tile from planes (plain word copies) ----
    {
        const int row = tid >> 1, e = tid & 1;
        const uint32_t* qh = (const uint32_t*)&g_qh[(size_t)(q0 + row) * (NH_ * HD_) + h * HD_ + e * 32];
        const uint32_t* ql = (const uint32_t*)&g_ql[(size_t)(q0 + row) * (NH_ * HD_) + h * HD_ + e * 32];
#pragma unroll
        for (int w = 0; w < 16; w++) {
            Qs[0][row * VSTR + e * 16 + w] = qh[w];
            Qs[1][row * VSTR + e * 16 + w] = ql[w];
        }
    }
    __syncthreads();

    // ---- Q fragments in registers ----
    uint32_t qa[2][4][4];
    {
        const int r0 = (wid * 16 + g) * VSTR;
        const int r8 = r0 + 8 * VSTR;
#pragma unroll
        for (int p = 0; p < 2; p++)
#pragma unroll
            for (int kt = 0; kt < 4; kt++) {
                const int w0 = kt * 8 + cq;
                qa[p][kt][0] = Qs[p][r0 + w0];
                qa[p][kt][1] = Qs[p][r8 + w0];
                qa[p][kt][2] = Qs[p][r0 + w0 + 4];
                qa[p][kt][3] = Qs[p][r8 + w0 + 4];
            }
    }

    float oacc[8][4];
#pragma unroll
    for (int nt = 0; nt < 8; nt++)
#pragma unroll
        for (int i = 0; i < 4; i++) oacc[nt][i] = 0.f;
    float m0 = -INFINITY, m8 = -INFINITY;
    float l0 = 0.f, l8 = 0.f;

    const int row_g  = q0 + wid * 16 + g;
    const int row_g8 = row_g + 8;
    const int ntiles = qt + 1;

    for (int t = 0; t < ntiles; t++) {
        const int k0 = t * 64;
        __syncthreads();

        // stage K tile from planes
        {
            const int key = tid >> 1, e = tid & 1;
            const uint32_t* kh = (const uint32_t*)&g_kh[(size_t)(k0 + key) * (NKV_ * HD_) + kv * HD_ + e * 32];
            const uint32_t* kl = (const uint32_t*)&g_kl[(size_t)(k0 + key) * (NKV_ * HD_) + kv * HD_ + e * 32];
#pragma unroll
            for (int w = 0; w < 16; w++) {
                Ks[0][key * VSTR + e * 16 + w] = kh[w];
                Ks[1][key * VSTR + e * 16 + w] = kl[w];
            }
        }
        // stage V transposed: Vs[dim][key-pair word] (split from fp32 g_qkv)
        {
            const int j = lane;
#pragma unroll
            for (int i = 0; i < 4; i++) {
                const int d = wid * 16 + i * 4;
                const float* v0 = &g_qkv[(size_t)(k0 + 2 * j) * QKV_N_ + VOFF_ + kv * HD_ + d];
                const float* v1 = v0 + QKV_N_;
                float4 a = *(const float4*)v0;
                float4 b = *(const float4*)v1;
                uint32_t hw, lw;
                split2(a.x, b.x, hw, lw); Vs[0][(d + 0) * VSTR + j] = hw; Vs[1][(d + 0) * VSTR + j] = lw;
                split2(a.y, b.y, hw, lw); Vs[0][(d + 1) * VSTR + j] = hw; Vs[1][(d + 1) * VSTR + j] = lw;
                split2(a.z, b.z, hw, lw); Vs[0][(d + 2) * VSTR + j] = hw; Vs[1][(d + 2) * VSTR + j] = lw;
                split2(a.w, b.w, hw, lw); Vs[0][(d + 3) * VSTR + j] = hw; Vs[1][(d + 3) * VSTR + j] = lw;
            }
        }
        __syncthreads();

        // ---- S = Q K^T ----
        float sacc[8][4];
#pragma unroll
        for (int nt = 0; nt < 8; nt++)
#pragma unroll
            for (int i = 0; i < 4; i++) sacc[nt][i] = 0.f;

#pragma unroll
        for (int kt = 0; kt < 4; kt++) {
#pragma unroll
            for (int nt = 0; nt < 8; nt++) {
                const int r0 = (nt * 8 + g) * VSTR + kt * 8 + cq;
                uint32_t bhf[2], blf[2];
                bhf[0] = Ks[0][r0]; bhf[1] = Ks[0][r0 + 4];
                blf[0] = Ks[1][r0]; blf[1] = Ks[1][r0 + 4];
                mma16816(sacc[nt], qa[0][kt], bhf);
                mma16816(sacc[nt], qa[0][kt], blf);
                mma16816(sacc[nt], qa[1][kt], bhf);
            }
        }

        // ---- scale + causal mask (last tile only) ----
        const bool last = (t == ntiles - 1);
#pragma unroll
        for (int nt = 0; nt < 8; nt++) {
            const int c0 = k0 + nt * 8 + 2 * cq;
#pragma unroll
            for (int i = 0; i < 4; i++) sacc[nt][i] *= SCALE_;
            if (last) {
                if (c0     > row_g)  sacc[nt][0] = -INFINITY;
                if (c0 + 1 > row_g)  sacc[nt][1] = -INFINITY;
                if (c0     > row_g8) sacc[nt][2] = -INFINITY;
                if (c0 + 1 > row_g8) sacc[nt][3] = -INFINITY;
            }
        }

        // ---- online softmax update ----
        float tm0 = -INFINITY, tm8 = -INFINITY;
#pragma unroll
        for (int nt = 0; nt < 8; nt++) {
            tm0 = fmaxf(tm0, fmaxf(sacc[nt][0], sacc[nt][1]));
            tm8 = fmaxf(tm8, fmaxf(sacc[nt][2], sacc[nt][3]));
        }
        tm0 = fmaxf(tm0, __shfl_xor_sync(0xffffffffu, tm0, 1));
        tm0 = fmaxf(tm0, __shfl_xor_sync(0xffffffffu, tm0, 2));
        tm8 = fmaxf(tm8, __shfl_xor_sync(0xffffffffu, tm8, 1));
        tm8 = fmaxf(tm8, __shfl_xor_sync(0xffffffffu, tm8, 2));

        const float m0n = fmaxf(m0, tm0);
        const float m8n = fmaxf(m8, tm8);
        const float a0 = __expf(m0 - m0n);
        const float a8 = __expf(m8 - m8n);
        m0 = m0n; m8 = m8n;
        l0 *= a0; l8 *= a8;
#pragma unroll
        for (int nt = 0; nt < 8; nt++) {
            oacc[nt][0] *= a0; oacc[nt][1] *= a0;
            oacc[nt][2] *= a8; oacc[nt][3] *= a8;
        }

#pragma unroll
        for (int nt = 0; nt < 8; nt++) {
            float p0 = (sacc[nt][0] == -INFINITY) ? 0.f : __expf(sacc[nt][0] - m0);
            float p1 = (sacc[nt][1] == -INFINITY) ? 0.f : __expf(sacc[nt][1] - m0);
            float p2 = (sacc[nt][2] == -INFINITY) ? 0.f : __expf(sacc[nt][2] - m8);
            float p3 = (sacc[nt][3] == -INFINITY) ? 0.f : __expf(sacc[nt][3] - m8);
            sacc[nt][0] = p0; sacc[nt][1] = p1; sacc[nt][2] = p2; sacc[nt][3] = p3;
            l0 += p0 + p1;
            l8 += p2 + p3;
        }

        // ---- O += P V ----
#pragma unroll
        for (int kt = 0; kt < 4; kt++) {
            uint32_t pah[4], pal[4];
            split2(sacc[2 * kt][0],     sacc[2 * kt][1],     pah[0], pal[0]);
            split2(sacc[2 * kt][2],     sacc[2 * kt][3],     pah[1], pal[1]);
            split2(sacc[2 * kt + 1][0], sacc[2 * kt + 1][1], pah[2], pal[2]);
            split2(sacc[2 * kt + 1][2], sacc[2 * kt + 1][3], pah[3], pal[3]);
#pragma unroll
            for (int nt = 0; nt < 8; nt++) {
                const int r0 = (nt * 8 + g) * VSTR + kt * 8 + cq;
                uint32_t vhf[2], vlf[2];
                vhf[0] = Vs[0][r0]; vhf[1] = Vs[0][r0 + 4];
                vlf[0] = Vs[1][r0]; vlf[1] = Vs[1][r0 + 4];
                mma16816(oacc[nt], pah, vhf);
                mma16816(oacc[nt], pah, vlf);
                mma16816(oacc[nt], pal, vhf);
            }
        }
    }

    // ---- finalize with sink; write bf16 hi/lo planes ----
    {
        const float m0n = fmaxf(m0, sink);
        const float m8n = fmaxf(m8, sink);
        const float a0 = __expf(m0 - m0n);
        const float a8 = __expf(m8 - m8n);
        l0 *= a0; l8 *= a8;
        l0 += __shfl_xor_sync(0xffffffffu, l0, 1);
        l0 += __shfl_xor_sync(0xffffffffu, l0, 2);
        l8 += __shfl_xor_sync(0xffffffffu, l8, 1);
        l8 += __shfl_xor_sync(0xffffffffu, l8, 2);
        const float inv0 = a0 / (l0 + __expf(sink - m0n));
        const float inv8 = a8 / (l8 + __expf(sink - m8n));
#pragma unroll
        for (int nt = 0; nt < 8; nt++) {
            const int col = h * HD_ + nt * 8 + 2 * cq;
            uint32_t hw, lw;
            split2(oacc[nt][0] * inv0, oacc[nt][1] * inv0, hw, lw);
            *(uint32_t*)&g_ah[(size_t)row_g * ATTN_N_ + col] = hw;
            *(uint32_t*)&g_al[(size_t)row_g * ATTN_N_ + col] = lw;
            split2(oacc[nt][2] * inv8, oacc[nt][3] * inv8, hw, lw);
            *(uint32_t*)&g_ah[(size_t)row_g8 * ATTN_N_ + col] = hw;
            *(uint32_t*)&g_al[(size_t)row_g8 * ATTN_N_ + col] = lw;
        }
    }
}

// ---------------------------------------------------------------------------
// Launch
// ---------------------------------------------------------------------------
extern "C" void kernel_launch(void* const* d_in, const int* in_sizes, int n_in,
                              void* d_out, int out_size)
{
    const int*   positions = (const int*)d_in[0];
    const float* hidden    = (const float*)d_in[1];
    const float* qkv_w     = (const float*)d_in[2];
    const float* o_w       = (const float*)d_in[3];
    const float* sinks     = (const float*)d_in[4];
    float*       out       = (float*)d_out;

    static bool attr_done = false;
    if (!attr_done) {
        cudaFuncSetAttribute(gemm_planes, cudaFuncAttributeMaxDynamicSharedMemorySize,
                             2 * BUF_ELEMS * (int)sizeof(__nv_bfloat16));
        attr_done = true;
    }

    void *p;
    cudaGetSymbolAddress(&p, g_qkv);  float* qkv = (float*)p;
    cudaGetSymbolAddress(&p, g_wqh);  __nv_bfloat16* wqh = (__nv_bfloat16*)p;
    cudaGetSymbolAddress(&p, g_wql);  __nv_bfloat16* wql = (__nv_bfloat16*)p;
    cudaGetSymbolAddress(&p, g_woh);  __nv_bfloat16* woh = (__nv_bfloat16*)p;
    cudaGetSymbolAddress(&p, g_wol);  __nv_bfloat16* wol = (__nv_bfloat16*)p;
    cudaGetSymbolAddress(&p, g_xh);   __nv_bfloat16* xh  = (__nv_bfloat16*)p;
    cudaGetSymbolAddress(&p, g_xl);   __nv_bfloat16* xl  = (__nv_bfloat16*)p;
    cudaGetSymbolAddress(&p, g_ah);   __nv_bfloat16* ah  = (__nv_bfloat16*)p;
    cudaGetSymbolAddress(&p, g_al);   __nv_bfloat16* al  = (__nv_bfloat16*)p;

    const int smem = 2 * BUF_ELEMS * (int)sizeof(__nv_bfloat16);

    // 0) pre-split weights + activations to bf16 planes
    split_f32<<<(QKV_N_ * H_) / 1024, 256>>>(qkv_w, wqh, wql, QKV_N_ * H_);
    split_f32<<<(H_ * ATTN_N_) / 1024, 256>>>(o_w, woh, wol, H_ * ATTN_N_);
    split_f32<<<(S_ * H_) / 1024, 256>>>(hidden, xh, xl, S_ * H_);

    // 1) QKV projection: [1024,2880] @ [5120,2880]^T -> g_qkv fp32
    gemm_planes<<<dim3(QKV_N_ / BN, S_ / BM), 256, smem>>>(xh, xl, wqh, wql, qkv, S_, QKV_N_, H_);

    // 2) RoPE + split Q/K to planes
    rope_split<<<S_ * (NH_ + NKV_), 32>>>(positions);

    // 3) Flash attention -> attn planes
    flash_attn<<<dim3(S_ / 64, NH_), 128>>>(sinks);

    // 4) O projection: attn planes @ o_w planes -> out fp32
    gemm_planes<<<dim3(H_ / BN, S_ / BM), 256, smem>>>(ah, al, woh, wol, out, S_, H_, ATTN_N_);
}

// round 9
// speedup vs baseline: 1.0041x; 1.0025x over previous
#include <cuda_runtime.h>
#include <cuda_bf16.h>
#include <math.h>
#include <stdint.h>

// Problem constants
#define S_   1024
#define H_   2880
#define NH_  64
#define NKV_ 8
#define HD_  64
#define QKV_N_ 5120              // (NH + 2*NKV) * HD
#define KOFF_  4096              // NH*HD
#define VOFF_  4608              // NH*HD + NKV*HD
#define ATTN_N_ 4096             // NH*HD
#define SCALE_ 0.125f            // HD^-0.5

// ---------------------------------------------------------------------------
// Scratch (allocation-free: __device__ globals)
// ---------------------------------------------------------------------------
__device__ float g_qkv[S_ * QKV_N_];                    // 20 MB (pre-rope)
__device__ __nv_bfloat16 g_wqh[QKV_N_ * H_];            // qkv_w hi plane
__device__ __nv_bfloat16 g_wql[QKV_N_ * H_];            // qkv_w lo plane
__device__ __nv_bfloat16 g_woh[H_ * ATTN_N_];           // o_w hi
__device__ __nv_bfloat16 g_wol[H_ * ATTN_N_];           // o_w lo
__device__ __nv_bfloat16 g_xh[S_ * H_];                 // hidden hi
__device__ __nv_bfloat16 g_xl[S_ * H_];                 // hidden lo
__device__ __nv_bfloat16 g_qh[S_ * NH_ * HD_];          // roped Q hi
__device__ __nv_bfloat16 g_ql[S_ * NH_ * HD_];
__device__ __nv_bfloat16 g_kh[S_ * NKV_ * HD_];         // roped K hi
__device__ __nv_bfloat16 g_kl[S_ * NKV_ * HD_];
__device__ __nv_bfloat16 g_ah[S_ * ATTN_N_];            // attn out hi
__device__ __nv_bfloat16 g_al[S_ * ATTN_N_];

// ---------------------------------------------------------------------------
// Helpers
// ---------------------------------------------------------------------------
__device__ __forceinline__ void mma16816(float* c, const uint32_t* a, const uint32_t* b) {
    asm volatile(
        "mma.sync.aligned.m16n8k16.row.col.f32.bf16.bf16.f32 "
        "{%0,%1,%2,%3}, {%4,%5,%6,%7}, {%8,%9}, {%0,%1,%2,%3};\n"
        : "+f"(c[0]), "+f"(c[1]), "+f"(c[2]), "+f"(c[3])
        : "r"(a[0]), "r"(a[1]), "r"(a[2]), "r"(a[3]), "r"(b[0]), "r"(b[1]));
}

__device__ __forceinline__ void split2(float x, float y, uint32_t& hi, uint32_t& lo) {
    __nv_bfloat16 hx = __float2bfloat16(x);
    __nv_bfloat16 hy = __float2bfloat16(y);
    __nv_bfloat16 lx = __float2bfloat16(x - __bfloat162float(hx));
    __nv_bfloat16 ly = __float2bfloat16(y - __bfloat162float(hy));
    hi = ((uint32_t)__bfloat16_as_ushort(hy) << 16) | (uint32_t)__bfloat16_as_ushort(hx);
    lo = ((uint32_t)__bfloat16_as_ushort(ly) << 16) | (uint32_t)__bfloat16_as_ushort(lx);
}

__device__ __forceinline__ uint32_t smemu32(const void* p) {
    return (uint32_t)__cvta_generic_to_shared(p);
}

#define LDSM4(R0, R1, R2, R3, addr) \
    asm volatile("ldmatrix.sync.aligned.m8n8.x4.shared.b16 {%0,%1,%2,%3}, [%4];" \
                 : "=r"(R0), "=r"(R1), "=r"(R2), "=r"(R3) : "r"(addr))

#define CP16(dst, src) \
    asm volatile("cp.async.cg.shared.global [%0], [%1], 16;" :: "r"(dst), "l"(src))

// ---------------------------------------------------------------------------
// fp32 -> bf16 hi/lo plane split (vectorized)
// ---------------------------------------------------------------------------
__global__ __launch_bounds__(256)
void split_f32(const float* __restrict__ in, __nv_bfloat16* __restrict__ hi,
               __nv_bfloat16* __restrict__ lo, int n)
{
    int i = (blockIdx.x * 256 + threadIdx.x) * 4;
    if (i >= n) return;
    float4 v = *(const float4*)&in[i];
    uint32_t h0, l0, h1, l1;
    split2(v.x, v.y, h0, l0);
    split2(v.z, v.w, h1, l1);
    uint32_t* ph = (uint32_t*)&hi[i];
    uint32_t* pl = (uint32_t*)&lo[i];
    ph[0] = h0; ph[1] = h1;
    pl[0] = l0; pl[1] = l1;
}

// ---------------------------------------------------------------------------
// Tensor-core GEMM (NT) on pre-split bf16 planes. 3-pass hi/lo.
// C[m,n] = sum_k A[m,k]*B[n,k].  BM=128, BN=64, BK=32, 256 thr (8 warps).
// cp.async double-buffered smem, ldmatrix fragment loads.
// ---------------------------------------------------------------------------
#define BM 128
#define BN 64
#define BK 32
#define ASTR 40                       // elems/row (32 data + 8 pad) = 80B, 16B-aligned, conflict-free
#define BUF_ELEMS (2 * BM * ASTR + 2 * BN * ASTR)   // 15360 elems = 30720 B per buffer

__global__ __launch_bounds__(256)
void gemm_planes(const __nv_bfloat16* __restrict__ Ah, const __nv_bfloat16* __restrict__ Al,
                 const __nv_bfloat16* __restrict__ Bh, const __nv_bfloat16* __restrict__ Bl,
                 float* __restrict__ C, int M, int N, int K)
{
    extern __shared__ __nv_bfloat16 sm[];    // [2][BUF_ELEMS]

    const int tid  = threadIdx.x;
    const int wid  = tid >> 5;
    const int lane = tid & 31;
    const int g    = lane >> 2;
    const int cq   = lane & 3;
    const int wm   = (wid & 3) * 32;
    const int wn   = (wid >> 2) * 32;
    const int bm   = blockIdx.y * BM;
    const int bn   = blockIdx.x * BN;

    float acc[2][4][4];
#pragma unroll
    for (int mt = 0; mt < 2; mt++)
#pragma unroll
        for (int nt = 0; nt < 4; nt++)
#pragma unroll
            for (int i = 0; i < 4; i++) acc[mt][nt][i] = 0.f;

    const int ntile = K / BK;

    // --- async tile loader: 6 x 16B per thread ---
    auto load_tile = [&](int t, int buf) {
        const int k0 = t * BK;
        __nv_bfloat16* s = sm + buf * BUF_ELEMS;
#pragma unroll
        for (int i = 0; i < 4; i++) {                  // A: 1024 chunks
            int c   = tid + i * 256;
            int p   = c >> 9;
            int r   = (c & 511) >> 2;
            int col = (c & 3) * 8;
            const __nv_bfloat16* src = (p ? Al : Ah) + (size_t)(bm + r) * K + k0 + col;
            CP16(smemu32(s + p * BM * ASTR + r * ASTR + col), src);
        }
#pragma unroll
        for (int i = 0; i < 2; i++) {                  // B: 512 chunks
            int c   = tid + i * 256;
            int p   = c >> 8;
            int r   = (c & 255) >> 2;
            int col = (c & 3) * 8;
            const __nv_bfloat16* src = (p ? Bl : Bh) + (size_t)(bn + r) * K + k0 + col;
            CP16(smemu32(s + 2 * BM * ASTR + p * BN * ASTR + r * ASTR + col), src);
        }
        asm volatile("cp.async.commit_group;" ::);
    };

    load_tile(0, 0);

    const int lr  = lane & 15;
    const int hb  = (lane >> 4) * 8;
    const int l8  = lane & 7;
    const int sel = lane >> 3;

    for (int t = 0; t < ntile; t++) {
        asm volatile("cp.async.wait_group 0;" ::);
        __syncthreads();
        if (t + 1 < ntile) load_tile(t + 1, (t + 1) & 1);

        const __nv_bfloat16* s = sm + (t & 1) * BUF_ELEMS;
#pragma unroll
        for (int kk = 0; kk < 2; kk++) {
            uint32_t ah[2][4], alv[2][4];
#pragma unroll
            for (int mt = 0; mt < 2; mt++) {
                uint32_t addr = smemu32(s + (wm + mt * 16 + lr) * ASTR + kk * 16 + hb);
                LDSM4(ah[mt][0], ah[mt][1], ah[mt][2], ah[mt][3], addr);
                addr = smemu32(s + BM * ASTR + (wm + mt * 16 + lr) * ASTR + kk * 16 + hb);
                LDSM4(alv[mt][0], alv[mt][1], alv[mt][2], alv[mt][3], addr);
            }
#pragma unroll
            for (int np = 0; np < 2; np++) {
                const int brow = wn + np * 16 + ((sel >> 1) << 3) + l8;
                const int bcol = kk * 16 + (sel & 1) * 8;
                uint32_t bh[4], bl[4];
                LDSM4(bh[0], bh[1], bh[2], bh[3],
                      smemu32(s + 2 * BM * ASTR + brow * ASTR + bcol));
                LDSM4(bl[0], bl[1], bl[2], bl[3],
                      smemu32(s + 2 * BM * ASTR + BN * ASTR + brow * ASTR + bcol));
#pragma unroll
                for (int mt = 0; mt < 2; mt++) {
                    mma16816(acc[mt][2 * np],     ah[mt],  &bh[0]);
                    mma16816(acc[mt][2 * np],     ah[mt],  &bl[0]);
                    mma16816(acc[mt][2 * np],     alv[mt], &bh[0]);
                    mma16816(acc[mt][2 * np + 1], ah[mt],  &bh[2]);
                    mma16816(acc[mt][2 * np + 1], ah[mt],  &bl[2]);
                    mma16816(acc[mt][2 * np + 1], alv[mt], &bh[2]);
                }
            }
        }
    }

#pragma unroll
    for (int mt = 0; mt < 2; mt++)
#pragma unroll
        for (int nt = 0; nt < 4; nt++) {
            int row = bm + wm + mt * 16 + g;
            int col = bn + wn + nt * 8 + cq * 2;
            *(float2*)&C[(size_t)row * N + col]       = make_float2(acc[mt][nt][0], acc[mt][nt][1]);
            *(float2*)&C[(size_t)(row + 8) * N + col] = make_float2(acc[mt][nt][2], acc[mt][nt][3]);
        }
}

// ---------------------------------------------------------------------------
// RoPE + split to bf16 planes. One 32-thread block per (s, q-or-k head).
// Reads g_qkv fp32 (pre-rope), writes g_qh/ql or g_kh/kl.
// ---------------------------------------------------------------------------
__global__ void rope_split(const int* __restrict__ positions)
{
    const int row = blockIdx.x;                  // 0 .. S*(NH+NKV)-1
    const int s  = row / (NH_ + NKV_);
    const int hh = row % (NH_ + NKV_);
    const int i  = threadIdx.x;                  // 0..31

    const float pos = (float)positions[s];
    const float inv_freq = powf(10000.0f, -(float)i / 32.0f);
    const float ang = pos * inv_freq;
    float c, sn;
    sincosf(ang, &sn, &c);

    const float* src;
    __nv_bfloat16 *dh, *dl;
    if (hh < NH_) {
        src = &g_qkv[(size_t)s * QKV_N_ + hh * HD_];
        dh = &g_qh[(size_t)s * (NH_ * HD_) + hh * HD_];
        dl = &g_ql[(size_t)s * (NH_ * HD_) + hh * HD_];
    } else {
        const int kvh = hh - NH_;
        src = &g_qkv[(size_t)s * QKV_N_ + KOFF_ + kvh * HD_];
        dh = &g_kh[(size_t)s * (NKV_ * HD_) + kvh * HD_];
        dl = &g_kl[(size_t)s * (NKV_ * HD_) + kvh * HD_];
    }
    const float x1 = src[i];
    const float x2 = src[i + 32];
    const float r1 = x1 * c - x2 * sn;
    const float r2 = x2 * c + x1 * sn;
    __nv_bfloat16 h1 = __float2bfloat16(r1);
    __nv_bfloat16 h2 = __float2bfloat16(r2);
    dh[i]      = h1;
    dh[i + 32] = h2;
    dl[i]      = __float2bfloat16(r1 - __bfloat162float(h1));
    dl[i + 32] = __float2bfloat16(r2 - __bfloat162float(h2));
}

// ---------------------------------------------------------------------------
// Flash attention (tensor cores, hi/lo 3-pass), online softmax, sinks.
// Q/K staged from pre-split planes; V split from g_qkv (transposed staging).
// Output written as bf16 hi/lo planes for the O-projection.
// ---------------------------------------------------------------------------
#define VSTR 36

__global__ __launch_bounds__(128)
void flash_attn(const float* __restrict__ sinks)
{
    __shared__ uint32_t Qs[2][64 * VSTR];
    __shared__ uint32_t Ks[2][64 * VSTR];
    __shared__ uint32_t Vs[2][64 * VSTR];

    const int h   = blockIdx.y;
    const int qt  = (S_ / 64 - 1) - blockIdx.x;   // heavy tiles first
    const int q0  = qt * 64;
    const int kv  = h >> 3;
    const int tid = threadIdx.x;
    const int wid = tid >> 5;
    const int lane = tid & 31;
    const int g   = lane >> 2;
    const int cq  = lane & 3;
    const float sink = sinks[h];

    // ---- stage Q tile from planes (plain word copies) ----
    {
        const int row = tid >> 1, e = tid & 1;
        const uint32_t* qh = (const uint32_t*)&g_qh[(size_t)(q0 + row) * (NH_ * HD_) + h * HD_ + e * 32];
        const uint32_t* ql = (const uint32_t*)&g_ql[(size_t)(q0 + row) * (NH_ * HD_) + h * HD_ + e * 32];
#pragma unroll
        for (int w = 0; w < 16; w++) {
            Qs[0][row * VSTR + e * 16 + w] = qh[w];
            Qs[1][row * VSTR + e * 16 + w] = ql[w];
        }
    }
    __syncthreads();

    // ---- Q fragments in registers ----
    uint32_t qa[2][4][4];
    {
        const int r0 = (wid * 16 + g) * VSTR;
        const int r8 = r0 + 8 * VSTR;
#pragma unroll
        for (int p = 0; p < 2; p++)
#pragma unroll
            for (int kt = 0; kt < 4; kt++) {
                const int w0 = kt * 8 + cq;
                qa[p][kt][0] = Qs[p][r0 + w0];
                qa[p][kt][1] = Qs[p][r8 + w0];
                qa[p][kt][2] = Qs[p][r0 + w0 + 4];
                qa[p][kt][3] = Qs[p][r8 + w0 + 4];
            }
    }

    float oacc[8][4];
#pragma unroll
    for (int nt = 0; nt < 8; nt++)
#pragma unroll
        for (int i = 0; i < 4; i++) oacc[nt][i] = 0.f;
    float m0 = -INFINITY, m8 = -INFINITY;
    float l0 = 0.f, l8 = 0.f;

    const int row_g  = q0 + wid * 16 + g;
    const int row_g8 = row_g + 8;
    const int ntiles = qt + 1;

    for (int t = 0; t < ntiles; t++) {
        const int k0 = t * 64;
        __syncthreads();

        // stage K tile from planes
        {
            const int key = tid >> 1, e = tid & 1;
            const uint32_t* kh = (const uint32_t*)&g_kh[(size_t)(k0 + key) * (NKV_ * HD_) + kv * HD_ + e * 32];
            const uint32_t* kl = (const uint32_t*)&g_kl[(size_t)(k0 + key) * (NKV_ * HD_) + kv * HD_ + e * 32];
#pragma unroll
            for (int w = 0; w < 16; w++) {
                Ks[0][key * VSTR + e * 16 + w] = kh[w];
                Ks[1][key * VSTR + e * 16 + w] = kl[w];
            }
        }
        // stage V transposed: Vs[dim][key-pair word] (split from fp32 g_qkv)
        {
            const int j = lane;
#pragma unroll
            for (int i = 0; i < 4; i++) {
                const int d = wid * 16 + i * 4;
                const float* v0 = &g_qkv[(size_t)(k0 + 2 * j) * QKV_N_ + VOFF_ + kv * HD_ + d];
                const float* v1 = v0 + QKV_N_;
                float4 a = *(const float4*)v0;
                float4 b = *(const float4*)v1;
                uint32_t hw, lw;
                split2(a.x, b.x, hw, lw); Vs[0][(d + 0) * VSTR + j] = hw; Vs[1][(d + 0) * VSTR + j] = lw;
                split2(a.y, b.y, hw, lw); Vs[0][(d + 1) * VSTR + j] = hw; Vs[1][(d + 1) * VSTR + j] = lw;
                split2(a.z, b.z, hw, lw); Vs[0][(d + 2) * VSTR + j] = hw; Vs[1][(d + 2) * VSTR + j] = lw;
                split2(a.w, b.w, hw, lw); Vs[0][(d + 3) * VSTR + j] = hw; Vs[1][(d + 3) * VSTR + j] = lw;
            }
        }
        __syncthreads();

        // ---- S = Q K^T ----
        float sacc[8][4];
#pragma unroll
        for (int nt = 0; nt < 8; nt++)
#pragma unroll
            for (int i = 0; i < 4; i++) sacc[nt][i] = 0.f;

#pragma unroll
        for (int kt = 0; kt < 4; kt++) {
#pragma unroll
            for (int nt = 0; nt < 8; nt++) {
                const int r0 = (nt * 8 + g) * VSTR + kt * 8 + cq;
                uint32_t bhf[2], blf[2];
                bhf[0] = Ks[0][r0]; bhf[1] = Ks[0][r0 + 4];
                blf[0] = Ks[1][r0]; blf[1] = Ks[1][r0 + 4];
                mma16816(sacc[nt], qa[0][kt], bhf);
                mma16816(sacc[nt], qa[0][kt], blf);
                mma16816(sacc[nt], qa[1][kt], bhf);
            }
        }

        // ---- scale + causal mask (last tile only) ----
        const bool last = (t == ntiles - 1);
#pragma unroll
        for (int nt = 0; nt < 8; nt++) {
            const int c0 = k0 + nt * 8 + 2 * cq;
#pragma unroll
            for (int i = 0; i < 4; i++) sacc[nt][i] *= SCALE_;
            if (last) {
                if (c0     > row_g)  sacc[nt][0] = -INFINITY;
                if (c0 + 1 > row_g)  sacc[nt][1] = -INFINITY;
                if (c0     > row_g8) sacc[nt][2] = -INFINITY;
                if (c0 + 1 > row_g8) sacc[nt][3] = -INFINITY;
            }
        }

        // ---- online softmax update ----
        float tm0 = -INFINITY, tm8 = -INFINITY;
#pragma unroll
        for (int nt = 0; nt < 8; nt++) {
            tm0 = fmaxf(tm0, fmaxf(sacc[nt][0], sacc[nt][1]));
            tm8 = fmaxf(tm8, fmaxf(sacc[nt][2], sacc[nt][3]));
        }
        tm0 = fmaxf(tm0, __shfl_xor_sync(0xffffffffu, tm0, 1));
        tm0 = fmaxf(tm0, __shfl_xor_sync(0xffffffffu, tm0, 2));
        tm8 = fmaxf(tm8, __shfl_xor_sync(0xffffffffu, tm8, 1));
        tm8 = fmaxf(tm8, __shfl_xor_sync(0xffffffffu, tm8, 2));

        const float m0n = fmaxf(m0, tm0);
        const float m8n = fmaxf(m8, tm8);
        const float a0 = __expf(m0 - m0n);
        const float a8 = __expf(m8 - m8n);
        m0 = m0n; m8 = m8n;
        l0 *= a0; l8 *= a8;
#pragma unroll
        for (int nt = 0; nt < 8; nt++) {
            oacc[nt][0] *= a0; oacc[nt][1] *= a0;
            oacc[nt][2] *= a8; oacc[nt][3] *= a8;
        }

#pragma unroll
        for (int nt = 0; nt < 8; nt++) {
            float p0 = (sacc[nt][0] == -INFINITY) ? 0.f : __expf(sacc[nt][0] - m0);
            float p1 = (sacc[nt][1] == -INFINITY) ? 0.f : __expf(sacc[nt][1] - m0);
            float p2 = (sacc[nt][2] == -INFINITY) ? 0.f : __expf(sacc[nt][2] - m8);
            float p3 = (sacc[nt][3] == -INFINITY) ? 0.f : __expf(sacc[nt][3] - m8);
            sacc[nt][0] = p0; sacc[nt][1] = p1; sacc[nt][2] = p2; sacc[nt][3] = p3;
            l0 += p0 + p1;
            l8 += p2 + p3;
        }

        // ---- O += P V ----
#pragma unroll
        for (int kt = 0; kt < 4; kt++) {
            uint32_t pah[4], pal[4];
            split2(sacc[2 * kt][0],     sacc[2 * kt][1],     pah[0], pal[0]);
            split2(sacc[2 * kt][2],     sacc[2 * kt][3],     pah[1], pal[1]);
            split2(sacc[2 * kt + 1][0], sacc[2 * kt + 1][1], pah[2], pal[2]);
            split2(sacc[2 * kt + 1][2], sacc[2 * kt + 1][3], pah[3], pal[3]);
#pragma unroll
            for (int nt = 0; nt < 8; nt++) {
                const int r0 = (nt * 8 + g) * VSTR + kt * 8 + cq;
                uint32_t vhf[2], vlf[2];
                vhf[0] = Vs[0][r0]; vhf[1] = Vs[0][r0 + 4];
                vlf[0] = Vs[1][r0]; vlf[1] = Vs[1][r0 + 4];
                mma16816(oacc[nt], pah, vhf);
                mma16816(oacc[nt], pah, vlf);
                mma16816(oacc[nt], pal, vhf);
            }
        }
    }

    // ---- finalize with sink; write bf16 hi/lo planes ----
    {
        const float m0n = fmaxf(m0, sink);
        const float m8n = fmaxf(m8, sink);
        const float a0 = __expf(m0 - m0n);
        const float a8 = __expf(m8 - m8n);
        l0 *= a0; l8 *= a8;
        l0 += __shfl_xor_sync(0xffffffffu, l0, 1);
        l0 += __shfl_xor_sync(0xffffffffu, l0, 2);
        l8 += __shfl_xor_sync(0xffffffffu, l8, 1);
        l8 += __shfl_xor_sync(0xffffffffu, l8, 2);
        const float inv0 = a0 / (l0 + __expf(sink - m0n));
        const float inv8 = a8 / (l8 + __expf(sink - m8n));
#pragma unroll
        for (int nt = 0; nt < 8; nt++) {
            const int col = h * HD_ + nt * 8 + 2 * cq;
            uint32_t hw, lw;
            split2(oacc[nt][0] * inv0, oacc[nt][1] * inv0, hw, lw);
            *(uint32_t*)&g_ah[(size_t)row_g * ATTN_N_ + col] = hw;
            *(uint32_t*)&g_al[(size_t)row_g * ATTN_N_ + col] = lw;
            split2(oacc[nt][2] * inv8, oacc[nt][3] * inv8, hw, lw);
            *(uint32_t*)&g_ah[(size_t)row_g8 * ATTN_N_ + col] = hw;
            *(uint32_t*)&g_al[(size_t)row_g8 * ATTN_N_ + col] = lw;
        }
    }
}

// ---------------------------------------------------------------------------
// Launch
// ---------------------------------------------------------------------------
extern "C" void kernel_launch(void* const* d_in, const int* in_sizes, int n_in,
                              void* d_out, int out_size)
{
    const int*   positions = (const int*)d_in[0];
    const float* hidden    = (const float*)d_in[1];
    const float* qkv_w     = (const float*)d_in[2];
    const float* o_w       = (const float*)d_in[3];
    const float* sinks     = (const float*)d_in[4];
    float*       out       = (float*)d_out;

    static bool attr_done = false;
    if (!attr_done) {
        cudaFuncSetAttribute(gemm_planes, cudaFuncAttributeMaxDynamicSharedMemorySize,
                             2 * BUF_ELEMS * (int)sizeof(__nv_bfloat16));
        attr_done = true;
    }

    void *p;
    cudaGetSymbolAddress(&p, g_qkv);  float* qkv = (float*)p;
    cudaGetSymbolAddress(&p, g_wqh);  __nv_bfloat16* wqh = (__nv_bfloat16*)p;
    cudaGetSymbolAddress(&p, g_wql);  __nv_bfloat16* wql = (__nv_bfloat16*)p;
    cudaGetSymbolAddress(&p, g_woh);  __nv_bfloat16* woh = (__nv_bfloat16*)p;
    cudaGetSymbolAddress(&p, g_wol);  __nv_bfloat16* wol = (__nv_bfloat16*)p;
    cudaGetSymbolAddress(&p, g_xh);   __nv_bfloat16* xh  = (__nv_bfloat16*)p;
    cudaGetSymbolAddress(&p, g_xl);   __nv_bfloat16* xl  = (__nv_bfloat16*)p;
    cudaGetSymbolAddress(&p, g_ah);   __nv_bfloat16* ah  = (__nv_bfloat16*)p;
    cudaGetSymbolAddress(&p, g_al);   __nv_bfloat16* al  = (__nv_bfloat16*)p;

    const int smem = 2 * BUF_ELEMS * (int)sizeof(__nv_bfloat16);

    // 0) pre-split weights + activations to bf16 planes
    split_f32<<<(QKV_N_ * H_) / 1024, 256>>>(qkv_w, wqh, wql, QKV_N_ * H_);
    split_f32<<<(H_ * ATTN_N_) / 1024, 256>>>(o_w, woh, wol, H_ * ATTN_N_);
    split_f32<<<(S_ * H_) / 1024, 256>>>(hidden, xh, xl, S_ * H_);

    // 1) QKV projection: [1024,2880] @ [5120,2880]^T -> g_qkv fp32
    gemm_planes<<<dim3(QKV_N_ / BN, S_ / BM), 256, smem>>>(xh, xl, wqh, wql, qkv, S_, QKV_N_, H_);

    // 2) RoPE + split Q/K to planes
    rope_split<<<S_ * (NH_ + NKV_), 32>>>(positions);

    // 3) Flash attention -> attn planes
    flash_attn<<<dim3(S_ / 64, NH_), 128>>>(sinks);

    // 4) O projection: attn planes @ o_w planes -> out fp32
    gemm_planes<<<dim3(H_ / BN, S_ / BM), 256, smem>>>(ah, al, woh, wol, out, S_, H_, ATTN_N_);
}